// round 10
// baseline (speedup 1.0000x reference)
#include <cuda_runtime.h>
#include <math.h>
#include <stdint.h>

// Problem constants
#define H_   16
#define DH_  64
#define DM_  1024
#define NSEQ 2048
#define BAT  2
#define MT   (BAT * NSEQ)   // 4096 total rows
#define KVLD 2048           // fused KV row width

// Scratch (device globals: allocation-free rule)
__device__ float g_Q[(size_t)MT * DM_];
__device__ float g_KV[(size_t)MT * KVLD];
__device__ float g_O[(size_t)MT * DM_];

// Packed f32x2 helpers (sm_103a; PTX ISA 8.6). IEEE fp32 per lane.
#define FMA_F32X2(d, a, b, c) \
    asm("fma.rn.f32x2 %0, %1, %2, %3;" : "=l"(d) : "l"(a), "l"(b), "l"(c))
#define MUL_F32X2(d, a, b) \
    asm("mul.rn.f32x2 %0, %1, %2;" : "=l"(d) : "l"(a), "l"(b))
#define PACK_F32X2(out, lo, hi) \
    asm("mov.b64 %0, {%1, %2};" : "=l"(out) : "r"(lo), "r"(hi))
#define UNPACK_F32X2(lo, hi, in) \
    asm("mov.b64 {%0, %1}, %2;" : "=r"(lo), "=r"(hi) : "l"(in))

// ---------------------------------------------------------------------------
// Shared GEMM body: C[bm:bm+128, bn:bn+128] = A[4096,1024] @ B[1024, ldb]
// BK=16, 256 threads, 8x8 per-thread tile, double-buffered smem, FFMA2.
// ---------------------------------------------------------------------------
__device__ __forceinline__ void gemm_body(
    const float* __restrict__ A, const float* __restrict__ Bw,
    int ldb, int bm, int bn, const float* __restrict__ bias,
    float* __restrict__ C,
    float (*As)[16][128], float (*Bs)[16][128])
{
    const int tid = threadIdx.x;
    const int ty = tid >> 4;          // 0..15 -> rows ty*8..
    const int tx = tid & 15;          // 0..15 -> cols tx*8..

    // load mapping (BK=16)
    const int arow = tid >> 1;        // 0..127
    const int akv  = (tid & 1) * 8;   // 0 or 8 (loads +0 and +4)
    const int brow = tid >> 5;        // 0..7  (also loads brow+8)
    const int bcol = (tid & 31) * 4;  // 0..124

    const float* Aptr = A + (size_t)(bm + arow) * 1024 + akv;
    const float* Bptr = Bw + (size_t)brow * ldb + bn + bcol;

    // Packed accumulators: acc2[i][j2] holds C(i, 2*j2 .. 2*j2+1)
    unsigned long long acc2[8][4];
#pragma unroll
    for (int i = 0; i < 8; i++)
#pragma unroll
        for (int j = 0; j < 4; j++) acc2[i][j] = 0ull;  // (0.f, 0.f)

    // Preload tile 0 into buffer 0
    {
        float4 a0 = *(const float4*)Aptr;
        float4 a1 = *(const float4*)(Aptr + 4);
        float4 b0 = *(const float4*)Bptr;
        float4 b1 = *(const float4*)(Bptr + (size_t)8 * ldb);
        As[0][akv + 0][arow] = a0.x; As[0][akv + 1][arow] = a0.y;
        As[0][akv + 2][arow] = a0.z; As[0][akv + 3][arow] = a0.w;
        As[0][akv + 4][arow] = a1.x; As[0][akv + 5][arow] = a1.y;
        As[0][akv + 6][arow] = a1.z; As[0][akv + 7][arow] = a1.w;
        *(float4*)&Bs[0][brow][bcol]     = b0;
        *(float4*)&Bs[0][brow + 8][bcol] = b1;
    }
    __syncthreads();

    const int NT = 1024 / 16;  // 64 K-tiles
    float4 a0_n, a1_n, b0_n, b1_n;
    for (int t = 0; t < NT; t++) {
        const int cur = t & 1;
        if (t < NT - 1) {
            const int k0 = (t + 1) * 16;
            a0_n = *(const float4*)(Aptr + k0);
            a1_n = *(const float4*)(Aptr + k0 + 4);
            b0_n = *(const float4*)(Bptr + (size_t)k0 * ldb);
            b1_n = *(const float4*)(Bptr + (size_t)(k0 + 8) * ldb);
        }

#pragma unroll
        for (int k = 0; k < 16; k++) {
            float ar[8], br[8];
            *(float4*)&ar[0] = *(const float4*)&As[cur][k][ty * 8];
            *(float4*)&ar[4] = *(const float4*)&As[cur][k][ty * 8 + 4];
            *(float4*)&br[0] = *(const float4*)&Bs[cur][k][tx * 8];
            *(float4*)&br[4] = *(const float4*)&Bs[cur][k][tx * 8 + 4];

            unsigned long long br2[4];
#pragma unroll
            for (int j = 0; j < 4; j++)
                PACK_F32X2(br2[j], __float_as_uint(br[2 * j]),
                                   __float_as_uint(br[2 * j + 1]));
#pragma unroll
            for (int i = 0; i < 8; i++) {
                unsigned long long a2;
                const unsigned int au = __float_as_uint(ar[i]);
                PACK_F32X2(a2, au, au);
#pragma unroll
                for (int j = 0; j < 4; j++)
                    FMA_F32X2(acc2[i][j], a2, br2[j], acc2[i][j]);
            }
        }

        if (t < NT - 1) {
            const int nxt = cur ^ 1;
            As[nxt][akv + 0][arow] = a0_n.x; As[nxt][akv + 1][arow] = a0_n.y;
            As[nxt][akv + 2][arow] = a0_n.z; As[nxt][akv + 3][arow] = a0_n.w;
            As[nxt][akv + 4][arow] = a1_n.x; As[nxt][akv + 5][arow] = a1_n.y;
            As[nxt][akv + 6][arow] = a1_n.z; As[nxt][akv + 7][arow] = a1_n.w;
            *(float4*)&Bs[nxt][brow][bcol]     = b0_n;
            *(float4*)&Bs[nxt][brow + 8][bcol] = b1_n;
            __syncthreads();
        }
    }

#pragma unroll
    for (int i = 0; i < 8; i++) {
        const int row = bm + ty * 8 + i;
        float out[8];
#pragma unroll
        for (int j = 0; j < 4; j++) {
            unsigned int lo, hi;
            UNPACK_F32X2(lo, hi, acc2[i][j]);
            out[2 * j]     = __uint_as_float(lo);
            out[2 * j + 1] = __uint_as_float(hi);
        }
#pragma unroll
        for (int j = 0; j < 8; j++) {
            float b = bias ? bias[bn + tx * 8 + j] : 0.f;
            out[j] += b;
        }
        *(float4*)&C[(size_t)row * ldb + bn + tx * 8]     = *(float4*)&out[0];
        *(float4*)&C[(size_t)row * ldb + bn + tx * 8 + 4] = *(float4*)&out[4];
    }
}

// Fused Q + KV projection: grid (24, 32). bx<8 -> Wq/g_Q, else Wkv/g_KV.
__global__ __launch_bounds__(256) void qkv_kernel(
    const float* __restrict__ X,
    const float* __restrict__ Wq, const float* __restrict__ Wkv)
{
    __shared__ float As[2][16][128];
    __shared__ float Bs[2][16][128];

    const int bxx = blockIdx.x;
    const int bm = blockIdx.y * 128;
    const float* Bw;
    float* C;
    int ldb, bn;
    if (bxx < 8) { Bw = Wq;  C = g_Q;  ldb = 1024; bn = bxx * 128; }
    else         { Bw = Wkv; C = g_KV; ldb = 2048; bn = (bxx - 8) * 128; }

    gemm_body(X, Bw, ldb, bm, bn, nullptr, C, As, Bs);
}

// Generic GEMM launch (used for the output projection, with bias).
__global__ __launch_bounds__(256) void gemm_kernel(
    const float* __restrict__ A, const float* __restrict__ Bw,
    int ldb, const float* __restrict__ bias,
    float* __restrict__ C)
{
    __shared__ float As[2][16][128];
    __shared__ float Bs[2][16][128];
    gemm_body(A, Bw, ldb, blockIdx.y * 128, blockIdx.x * 128, bias, C, As, Bs);
}

// ---------------------------------------------------------------------------
// Flash attention, fp32 (packed f32x2 GEMM loops — fp32 math throughout).
// One block = 64 query rows of one (batch, head). 256 threads (16x16);
// each thread owns 4x4 of S and 4x4 of O (O accumulators packed).
// Q is pre-scaled by DH^-0.5 (exact power-of-two) at load.
// K/V tiles are register double-buffered: LDG for tile t+1 issues before
// tile t's compute, hiding L2 latency under the whole compute phase.
// ---------------------------------------------------------------------------
#define APITCH 68
#define ASMEM  (3 * 64 * APITCH * 4)   // 52224 bytes

__global__ __launch_bounds__(256) void attn_kernel()
{
    extern __shared__ float smem[];
    float* Qs = smem;                    // [64][APITCH]  (row idx = d, col = q-row)
    float* KP = smem + 64 * APITCH;      // [64][APITCH]  (K^T then P)
    float* Vs = smem + 2 * 64 * APITCH;  // [64][APITCH]  (row idx = key, col = d)

    const int tid = threadIdx.x;
    const int ty = tid >> 4;   // 0..15 -> q-rows ty*4..
    const int tx = tid & 15;   // 0..15 -> key/d cols tx*4..
    const int qt = blockIdx.x;
    const int h  = blockIdx.y;
    const int b  = blockIdx.z;
    const int q0 = qt * 64;

    const float* Qg = g_Q  + (size_t)b * NSEQ * DM_  + (size_t)h * DH_;
    const float* Kg = g_KV + (size_t)b * NSEQ * KVLD + (size_t)h * DH_;
    const float* Vg = Kg + 1024;
    float*       Og = g_O  + (size_t)b * NSEQ * DM_  + (size_t)h * DH_;

    // Per-thread K/V load coordinates (4 chunks of float4 each)
    const int lkey = tid >> 4;          // 0..15 base key row (stride 16 over i)
    const int ldv  = (tid & 15) * 4;    // d offset

    // Load Q tile transposed into Qs[d][row], pre-scaled by 0.125 (= DH^-0.5)
#pragma unroll
    for (int i = 0; i < 4; i++) {
        int row = lkey + i * 16;
        float4 v = *(const float4*)&Qg[(size_t)(q0 + row) * DM_ + ldv];
        Qs[(ldv + 0) * APITCH + row] = v.x * 0.125f;
        Qs[(ldv + 1) * APITCH + row] = v.y * 0.125f;
        Qs[(ldv + 2) * APITCH + row] = v.z * 0.125f;
        Qs[(ldv + 3) * APITCH + row] = v.w * 0.125f;
    }

    // Preload K/V tile 0 into registers
    float4 kreg[4], vreg[4];
#pragma unroll
    for (int i = 0; i < 4; i++) {
        int key = lkey + i * 16;
        kreg[i] = *(const float4*)&Kg[(size_t)key * KVLD + ldv];
        vreg[i] = *(const float4*)&Vg[(size_t)key * KVLD + ldv];
    }

    float m[4], l[4];
    unsigned long long acc2[4][2];   // packed O accumulators
#pragma unroll
    for (int i = 0; i < 4; i++) {
        m[i] = -INFINITY; l[i] = 0.f;
        acc2[i][0] = 0ull; acc2[i][1] = 0ull;
    }

    const int NKT = NSEQ / 64;
    for (int kt = 0; kt < NKT; kt++) {
        __syncthreads();  // previous iteration's reads of KP/Vs done
        // Store registers (tile kt): K transposed -> KP[d][key], V -> Vs[key][d]
#pragma unroll
        for (int i = 0; i < 4; i++) {
            int key = lkey + i * 16;
            KP[(ldv + 0) * APITCH + key] = kreg[i].x;
            KP[(ldv + 1) * APITCH + key] = kreg[i].y;
            KP[(ldv + 2) * APITCH + key] = kreg[i].z;
            KP[(ldv + 3) * APITCH + key] = kreg[i].w;
            *(float4*)&Vs[key * APITCH + ldv] = vreg[i];
        }
        __syncthreads();

        // Prefetch tile kt+1 into registers (consumed at next iteration's STS)
        if (kt + 1 < NKT) {
            const int kb = (kt + 1) * 64;
#pragma unroll
            for (int i = 0; i < 4; i++) {
                int key = kb + lkey + i * 16;
                kreg[i] = *(const float4*)&Kg[(size_t)key * KVLD + ldv];
                vreg[i] = *(const float4*)&Vg[(size_t)key * KVLD + ldv];
            }
        }

        // S = (Q*scale) @ K^T  (packed: s2[i][j2] = S(i, 2j2..2j2+1))
        unsigned long long s2[4][2];
#pragma unroll
        for (int i = 0; i < 4; i++) { s2[i][0] = 0ull; s2[i][1] = 0ull; }
#pragma unroll 8
        for (int d = 0; d < 64; d++) {
            float4 qv = *(const float4*)&Qs[d * APITCH + ty * 4];
            float4 kv = *(const float4*)&KP[d * APITCH + tx * 4];
            unsigned long long k2[2];
            PACK_F32X2(k2[0], __float_as_uint(kv.x), __float_as_uint(kv.y));
            PACK_F32X2(k2[1], __float_as_uint(kv.z), __float_as_uint(kv.w));
            const float qa[4] = {qv.x, qv.y, qv.z, qv.w};
#pragma unroll
            for (int i = 0; i < 4; i++) {
                unsigned long long q2;
                const unsigned int qu = __float_as_uint(qa[i]);
                PACK_F32X2(q2, qu, qu);
                FMA_F32X2(s2[i][0], q2, k2[0], s2[i][0]);
                FMA_F32X2(s2[i][1], q2, k2[1], s2[i][1]);
            }
        }

        // Unpack S, online softmax per q-row (reduce across 16 tx lanes)
        float s[4][4];
#pragma unroll
        for (int i = 0; i < 4; i++) {
            unsigned int lo, hi;
            UNPACK_F32X2(lo, hi, s2[i][0]);
            s[i][0] = __uint_as_float(lo); s[i][1] = __uint_as_float(hi);
            UNPACK_F32X2(lo, hi, s2[i][1]);
            s[i][2] = __uint_as_float(lo); s[i][3] = __uint_as_float(hi);
        }
#pragma unroll
        for (int i = 0; i < 4; i++) {
            float tmax = fmaxf(fmaxf(s[i][0], s[i][1]), fmaxf(s[i][2], s[i][3]));
#pragma unroll
            for (int off = 8; off > 0; off >>= 1)
                tmax = fmaxf(tmax, __shfl_xor_sync(0xffffffffu, tmax, off));
            float mnew = fmaxf(m[i], tmax);
            float corr = __expf(m[i] - mnew);
            float tsum = 0.f;
#pragma unroll
            for (int j = 0; j < 4; j++) {
                s[i][j] = __expf(s[i][j] - mnew);
                tsum += s[i][j];
            }
#pragma unroll
            for (int off = 8; off > 0; off >>= 1)
                tsum += __shfl_xor_sync(0xffffffffu, tsum, off);
            l[i] = l[i] * corr + tsum;
            m[i] = mnew;
            unsigned long long c2;
            const unsigned int cu = __float_as_uint(corr);
            PACK_F32X2(c2, cu, cu);
            MUL_F32X2(acc2[i][0], acc2[i][0], c2);
            MUL_F32X2(acc2[i][1], acc2[i][1], c2);
        }

        __syncthreads();  // all S reads of KP done before P overwrite
        // Stage P into KP as [key][q-row]
#pragma unroll
        for (int j = 0; j < 4; j++) {
            float4 pv = make_float4(s[0][j], s[1][j], s[2][j], s[3][j]);
            *(float4*)&KP[(tx * 4 + j) * APITCH + ty * 4] = pv;
        }
        __syncthreads();

        // O += P @ V (packed over the d/output columns)
#pragma unroll 8
        for (int k = 0; k < 64; k++) {
            float4 pv = *(const float4*)&KP[k * APITCH + ty * 4];
            float4 vv = *(const float4*)&Vs[k * APITCH + tx * 4];
            unsigned long long v2[2];
            PACK_F32X2(v2[0], __float_as_uint(vv.x), __float_as_uint(vv.y));
            PACK_F32X2(v2[1], __float_as_uint(vv.z), __float_as_uint(vv.w));
            const float pa[4] = {pv.x, pv.y, pv.z, pv.w};
#pragma unroll
            for (int i = 0; i < 4; i++) {
                unsigned long long p2;
                const unsigned int pu = __float_as_uint(pa[i]);
                PACK_F32X2(p2, pu, pu);
                FMA_F32X2(acc2[i][0], p2, v2[0], acc2[i][0]);
                FMA_F32X2(acc2[i][1], p2, v2[1], acc2[i][1]);
            }
        }
    }

    // Normalize and store
#pragma unroll
    for (int i = 0; i < 4; i++) {
        float inv = 1.0f / l[i];
        unsigned int lo, hi;
        float o[4];
        UNPACK_F32X2(lo, hi, acc2[i][0]);
        o[0] = __uint_as_float(lo) * inv; o[1] = __uint_as_float(hi) * inv;
        UNPACK_F32X2(lo, hi, acc2[i][1]);
        o[2] = __uint_as_float(lo) * inv; o[3] = __uint_as_float(hi) * inv;
        *(float4*)&Og[(size_t)(q0 + ty * 4 + i) * DM_ + tx * 4] =
            make_float4(o[0], o[1], o[2], o[3]);
    }
}

// ---------------------------------------------------------------------------
extern "C" void kernel_launch(void* const* d_in, const int* in_sizes, int n_in,
                              void* d_out, int out_size)
{
    const float* X   = (const float*)d_in[0];  // queries [2,2048,1024]
    const float* Wq  = (const float*)d_in[1];  // [1024,1024]
    const float* Wkv = (const float*)d_in[2];  // [1024,2048]
    const float* Wo  = (const float*)d_in[3];  // [1024,1024]
    const float* bo  = (const float*)d_in[4];  // [1024]
    float* out = (float*)d_out;
    (void)in_sizes; (void)n_in; (void)out_size;

    float* o;
    cudaGetSymbolAddress((void**)&o, g_O);

    cudaFuncSetAttribute(attn_kernel,
                         cudaFuncAttributeMaxDynamicSharedMemorySize, ASMEM);

    qkv_kernel<<<dim3(24, 32), 256>>>(X, Wq, Wkv);          // Q + K + V proj
    attn_kernel<<<dim3(32, 16, 2), 256, ASMEM>>>();
    gemm_kernel<<<dim3(8, 32), 256>>>(o, Wo, 1024, bo, out); // out proj
}

// round 12
// speedup vs baseline: 1.0423x; 1.0423x over previous
#include <cuda_runtime.h>
#include <math.h>
#include <stdint.h>

// Problem constants
#define H_   16
#define DH_  64
#define DM_  1024
#define NSEQ 2048
#define BAT  2
#define MT   (BAT * NSEQ)   // 4096 total rows
#define KVLD 2048           // fused KV row width

// Scratch (device globals: allocation-free rule)
__device__ float g_Q[(size_t)MT * DM_];
__device__ float g_KV[(size_t)MT * KVLD];
__device__ float g_O[(size_t)MT * DM_];

// Packed f32x2 helpers (sm_103a; PTX ISA 8.6). IEEE fp32 per lane.
#define FMA_F32X2(d, a, b, c) \
    asm("fma.rn.f32x2 %0, %1, %2, %3;" : "=l"(d) : "l"(a), "l"(b), "l"(c))
#define MUL_F32X2(d, a, b) \
    asm("mul.rn.f32x2 %0, %1, %2;" : "=l"(d) : "l"(a), "l"(b))
#define PACK_F32X2(out, lo, hi) \
    asm("mov.b64 %0, {%1, %2};" : "=l"(out) : "r"(lo), "r"(hi))
#define UNPACK_F32X2(lo, hi, in) \
    asm("mov.b64 {%0, %1}, %2;" : "=r"(lo), "=r"(hi) : "l"(in))

// ---------------------------------------------------------------------------
// Shared GEMM body: C[bm:bm+128, bn:bn+128] = A[4096,1024] @ B[1024, ldb]
// BK=16, 256 threads, 8x8 per-thread tile, double-buffered smem, FFMA2.
// ---------------------------------------------------------------------------
__device__ __forceinline__ void gemm_body(
    const float* __restrict__ A, const float* __restrict__ Bw,
    int ldb, int bm, int bn, const float* __restrict__ bias,
    float* __restrict__ C,
    float (*As)[16][128], float (*Bs)[16][128])
{
    const int tid = threadIdx.x;
    const int ty = tid >> 4;          // 0..15 -> rows ty*8..
    const int tx = tid & 15;          // 0..15 -> cols tx*8..

    // load mapping (BK=16)
    const int arow = tid >> 1;        // 0..127
    const int akv  = (tid & 1) * 8;   // 0 or 8 (loads +0 and +4)
    const int brow = tid >> 5;        // 0..7  (also loads brow+8)
    const int bcol = (tid & 31) * 4;  // 0..124

    const float* Aptr = A + (size_t)(bm + arow) * 1024 + akv;
    const float* Bptr = Bw + (size_t)brow * ldb + bn + bcol;

    // Packed accumulators: acc2[i][j2] holds C(i, 2*j2 .. 2*j2+1)
    unsigned long long acc2[8][4];
#pragma unroll
    for (int i = 0; i < 8; i++)
#pragma unroll
        for (int j = 0; j < 4; j++) acc2[i][j] = 0ull;  // (0.f, 0.f)

    // Preload tile 0 into buffer 0
    {
        float4 a0 = *(const float4*)Aptr;
        float4 a1 = *(const float4*)(Aptr + 4);
        float4 b0 = *(const float4*)Bptr;
        float4 b1 = *(const float4*)(Bptr + (size_t)8 * ldb);
        As[0][akv + 0][arow] = a0.x; As[0][akv + 1][arow] = a0.y;
        As[0][akv + 2][arow] = a0.z; As[0][akv + 3][arow] = a0.w;
        As[0][akv + 4][arow] = a1.x; As[0][akv + 5][arow] = a1.y;
        As[0][akv + 6][arow] = a1.z; As[0][akv + 7][arow] = a1.w;
        *(float4*)&Bs[0][brow][bcol]     = b0;
        *(float4*)&Bs[0][brow + 8][bcol] = b1;
    }
    __syncthreads();

    const int NT = 1024 / 16;  // 64 K-tiles
    float4 a0_n, a1_n, b0_n, b1_n;
    for (int t = 0; t < NT; t++) {
        const int cur = t & 1;
        if (t < NT - 1) {
            const int k0 = (t + 1) * 16;
            a0_n = *(const float4*)(Aptr + k0);
            a1_n = *(const float4*)(Aptr + k0 + 4);
            b0_n = *(const float4*)(Bptr + (size_t)k0 * ldb);
            b1_n = *(const float4*)(Bptr + (size_t)(k0 + 8) * ldb);
        }

#pragma unroll
        for (int k = 0; k < 16; k++) {
            float ar[8], br[8];
            *(float4*)&ar[0] = *(const float4*)&As[cur][k][ty * 8];
            *(float4*)&ar[4] = *(const float4*)&As[cur][k][ty * 8 + 4];
            *(float4*)&br[0] = *(const float4*)&Bs[cur][k][tx * 8];
            *(float4*)&br[4] = *(const float4*)&Bs[cur][k][tx * 8 + 4];

            unsigned long long br2[4];
#pragma unroll
            for (int j = 0; j < 4; j++)
                PACK_F32X2(br2[j], __float_as_uint(br[2 * j]),
                                   __float_as_uint(br[2 * j + 1]));
#pragma unroll
            for (int i = 0; i < 8; i++) {
                unsigned long long a2;
                const unsigned int au = __float_as_uint(ar[i]);
                PACK_F32X2(a2, au, au);
#pragma unroll
                for (int j = 0; j < 4; j++)
                    FMA_F32X2(acc2[i][j], a2, br2[j], acc2[i][j]);
            }
        }

        if (t < NT - 1) {
            const int nxt = cur ^ 1;
            As[nxt][akv + 0][arow] = a0_n.x; As[nxt][akv + 1][arow] = a0_n.y;
            As[nxt][akv + 2][arow] = a0_n.z; As[nxt][akv + 3][arow] = a0_n.w;
            As[nxt][akv + 4][arow] = a1_n.x; As[nxt][akv + 5][arow] = a1_n.y;
            As[nxt][akv + 6][arow] = a1_n.z; As[nxt][akv + 7][arow] = a1_n.w;
            *(float4*)&Bs[nxt][brow][bcol]     = b0_n;
            *(float4*)&Bs[nxt][brow + 8][bcol] = b1_n;
            __syncthreads();
        }
    }

#pragma unroll
    for (int i = 0; i < 8; i++) {
        const int row = bm + ty * 8 + i;
        float out[8];
#pragma unroll
        for (int j = 0; j < 4; j++) {
            unsigned int lo, hi;
            UNPACK_F32X2(lo, hi, acc2[i][j]);
            out[2 * j]     = __uint_as_float(lo);
            out[2 * j + 1] = __uint_as_float(hi);
        }
#pragma unroll
        for (int j = 0; j < 8; j++) {
            float b = bias ? bias[bn + tx * 8 + j] : 0.f;
            out[j] += b;
        }
        *(float4*)&C[(size_t)row * ldb + bn + tx * 8]     = *(float4*)&out[0];
        *(float4*)&C[(size_t)row * ldb + bn + tx * 8 + 4] = *(float4*)&out[4];
    }
}

// Fused Q + KV projection: grid (24, 32). bx<8 -> Wq/g_Q, else Wkv/g_KV.
__global__ __launch_bounds__(256, 2) void qkv_kernel(
    const float* __restrict__ X,
    const float* __restrict__ Wq, const float* __restrict__ Wkv)
{
    __shared__ float As[2][16][128];
    __shared__ float Bs[2][16][128];

    const int bxx = blockIdx.x;
    const int bm = blockIdx.y * 128;
    const float* Bw;
    float* C;
    int ldb, bn;
    if (bxx < 8) { Bw = Wq;  C = g_Q;  ldb = 1024; bn = bxx * 128; }
    else         { Bw = Wkv; C = g_KV; ldb = 2048; bn = (bxx - 8) * 128; }

    gemm_body(X, Bw, ldb, bm, bn, nullptr, C, As, Bs);
}

// Generic GEMM launch (used for the output projection, with bias).
__global__ __launch_bounds__(256, 2) void gemm_kernel(
    const float* __restrict__ A, const float* __restrict__ Bw,
    int ldb, const float* __restrict__ bias,
    float* __restrict__ C)
{
    __shared__ float As[2][16][128];
    __shared__ float Bs[2][16][128];
    gemm_body(A, Bw, ldb, blockIdx.y * 128, blockIdx.x * 128, bias, C, As, Bs);
}

// ---------------------------------------------------------------------------
// Flash attention, fp32 (packed f32x2 GEMM loops — fp32 math throughout).
// One block = 64 query rows of one (batch, head). 256 threads (16x16);
// each thread owns 4x4 of S and 4x4 of O (O accumulators packed).
// Q is pre-scaled by DH^-0.5 (exact power-of-two) at load.
// K/V tiles are register double-buffered: LDG for tile t+1 issues before
// tile t's compute, hiding L2 latency under the whole compute phase.
// ---------------------------------------------------------------------------
#define APITCH 68
#define ASMEM  (3 * 64 * APITCH * 4)   // 52224 bytes

__global__ __launch_bounds__(256, 2) void attn_kernel()
{
    extern __shared__ float smem[];
    float* Qs = smem;                    // [64][APITCH]  (row idx = d, col = q-row)
    float* KP = smem + 64 * APITCH;      // [64][APITCH]  (K^T then P)
    float* Vs = smem + 2 * 64 * APITCH;  // [64][APITCH]  (row idx = key, col = d)

    const int tid = threadIdx.x;
    const int ty = tid >> 4;   // 0..15 -> q-rows ty*4..
    const int tx = tid & 15;   // 0..15 -> key/d cols tx*4..
    const int qt = blockIdx.x;
    const int h  = blockIdx.y;
    const int b  = blockIdx.z;
    const int q0 = qt * 64;

    const float* Qg = g_Q  + (size_t)b * NSEQ * DM_  + (size_t)h * DH_;
    const float* Kg = g_KV + (size_t)b * NSEQ * KVLD + (size_t)h * DH_;
    const float* Vg = Kg + 1024;
    float*       Og = g_O  + (size_t)b * NSEQ * DM_  + (size_t)h * DH_;

    // Per-thread K/V load coordinates (4 chunks of float4 each)
    const int lkey = tid >> 4;          // 0..15 base key row (stride 16 over i)
    const int ldv  = (tid & 15) * 4;    // d offset

    // Load Q tile transposed into Qs[d][row], pre-scaled by 0.125 (= DH^-0.5)
#pragma unroll
    for (int i = 0; i < 4; i++) {
        int row = lkey + i * 16;
        float4 v = *(const float4*)&Qg[(size_t)(q0 + row) * DM_ + ldv];
        Qs[(ldv + 0) * APITCH + row] = v.x * 0.125f;
        Qs[(ldv + 1) * APITCH + row] = v.y * 0.125f;
        Qs[(ldv + 2) * APITCH + row] = v.z * 0.125f;
        Qs[(ldv + 3) * APITCH + row] = v.w * 0.125f;
    }

    // Preload K/V tile 0 into registers
    float4 kreg[4], vreg[4];
#pragma unroll
    for (int i = 0; i < 4; i++) {
        int key = lkey + i * 16;
        kreg[i] = *(const float4*)&Kg[(size_t)key * KVLD + ldv];
        vreg[i] = *(const float4*)&Vg[(size_t)key * KVLD + ldv];
    }

    float m[4], l[4];
    unsigned long long acc2[4][2];   // packed O accumulators
#pragma unroll
    for (int i = 0; i < 4; i++) {
        m[i] = -INFINITY; l[i] = 0.f;
        acc2[i][0] = 0ull; acc2[i][1] = 0ull;
    }

    const int NKT = NSEQ / 64;
    for (int kt = 0; kt < NKT; kt++) {
        __syncthreads();  // previous iteration's reads of KP/Vs done
        // Store registers (tile kt): K transposed -> KP[d][key], V -> Vs[key][d]
#pragma unroll
        for (int i = 0; i < 4; i++) {
            int key = lkey + i * 16;
            KP[(ldv + 0) * APITCH + key] = kreg[i].x;
            KP[(ldv + 1) * APITCH + key] = kreg[i].y;
            KP[(ldv + 2) * APITCH + key] = kreg[i].z;
            KP[(ldv + 3) * APITCH + key] = kreg[i].w;
            *(float4*)&Vs[key * APITCH + ldv] = vreg[i];
        }
        __syncthreads();

        // Prefetch tile kt+1 into registers (consumed at next iteration's STS)
        if (kt + 1 < NKT) {
            const int kb = (kt + 1) * 64;
#pragma unroll
            for (int i = 0; i < 4; i++) {
                int key = kb + lkey + i * 16;
                kreg[i] = *(const float4*)&Kg[(size_t)key * KVLD + ldv];
                vreg[i] = *(const float4*)&Vg[(size_t)key * KVLD + ldv];
            }
        }

        // S = (Q*scale) @ K^T  (packed: s2[i][j2] = S(i, 2j2..2j2+1))
        unsigned long long s2[4][2];
#pragma unroll
        for (int i = 0; i < 4; i++) { s2[i][0] = 0ull; s2[i][1] = 0ull; }
#pragma unroll 8
        for (int d = 0; d < 64; d++) {
            float4 qv = *(const float4*)&Qs[d * APITCH + ty * 4];
            float4 kv = *(const float4*)&KP[d * APITCH + tx * 4];
            unsigned long long k2[2];
            PACK_F32X2(k2[0], __float_as_uint(kv.x), __float_as_uint(kv.y));
            PACK_F32X2(k2[1], __float_as_uint(kv.z), __float_as_uint(kv.w));
            const float qa[4] = {qv.x, qv.y, qv.z, qv.w};
#pragma unroll
            for (int i = 0; i < 4; i++) {
                unsigned long long q2;
                const unsigned int qu = __float_as_uint(qa[i]);
                PACK_F32X2(q2, qu, qu);
                FMA_F32X2(s2[i][0], q2, k2[0], s2[i][0]);
                FMA_F32X2(s2[i][1], q2, k2[1], s2[i][1]);
            }
        }

        // Unpack S, online softmax per q-row (reduce across 16 tx lanes)
        float s[4][4];
#pragma unroll
        for (int i = 0; i < 4; i++) {
            unsigned int lo, hi;
            UNPACK_F32X2(lo, hi, s2[i][0]);
            s[i][0] = __uint_as_float(lo); s[i][1] = __uint_as_float(hi);
            UNPACK_F32X2(lo, hi, s2[i][1]);
            s[i][2] = __uint_as_float(lo); s[i][3] = __uint_as_float(hi);
        }
#pragma unroll
        for (int i = 0; i < 4; i++) {
            float tmax = fmaxf(fmaxf(s[i][0], s[i][1]), fmaxf(s[i][2], s[i][3]));
#pragma unroll
            for (int off = 8; off > 0; off >>= 1)
                tmax = fmaxf(tmax, __shfl_xor_sync(0xffffffffu, tmax, off));
            float mnew = fmaxf(m[i], tmax);
            float corr = __expf(m[i] - mnew);
            float tsum = 0.f;
#pragma unroll
            for (int j = 0; j < 4; j++) {
                s[i][j] = __expf(s[i][j] - mnew);
                tsum += s[i][j];
            }
#pragma unroll
            for (int off = 8; off > 0; off >>= 1)
                tsum += __shfl_xor_sync(0xffffffffu, tsum, off);
            l[i] = l[i] * corr + tsum;
            m[i] = mnew;
            unsigned long long c2;
            const unsigned int cu = __float_as_uint(corr);
            PACK_F32X2(c2, cu, cu);
            MUL_F32X2(acc2[i][0], acc2[i][0], c2);
            MUL_F32X2(acc2[i][1], acc2[i][1], c2);
        }

        __syncthreads();  // all S reads of KP done before P overwrite
        // Stage P into KP as [key][q-row]
#pragma unroll
        for (int j = 0; j < 4; j++) {
            float4 pv = make_float4(s[0][j], s[1][j], s[2][j], s[3][j]);
            *(float4*)&KP[(tx * 4 + j) * APITCH + ty * 4] = pv;
        }
        __syncthreads();

        // O += P @ V (packed over the d/output columns)
#pragma unroll 8
        for (int k = 0; k < 64; k++) {
            float4 pv = *(const float4*)&KP[k * APITCH + ty * 4];
            float4 vv = *(const float4*)&Vs[k * APITCH + tx * 4];
            unsigned long long v2[2];
            PACK_F32X2(v2[0], __float_as_uint(vv.x), __float_as_uint(vv.y));
            PACK_F32X2(v2[1], __float_as_uint(vv.z), __float_as_uint(vv.w));
            const float pa[4] = {pv.x, pv.y, pv.z, pv.w};
#pragma unroll
            for (int i = 0; i < 4; i++) {
                unsigned long long p2;
                const unsigned int pu = __float_as_uint(pa[i]);
                PACK_F32X2(p2, pu, pu);
                FMA_F32X2(acc2[i][0], p2, v2[0], acc2[i][0]);
                FMA_F32X2(acc2[i][1], p2, v2[1], acc2[i][1]);
            }
        }
    }

    // Normalize and store
#pragma unroll
    for (int i = 0; i < 4; i++) {
        float inv = 1.0f / l[i];
        unsigned int lo, hi;
        float o[4];
        UNPACK_F32X2(lo, hi, acc2[i][0]);
        o[0] = __uint_as_float(lo) * inv; o[1] = __uint_as_float(hi) * inv;
        UNPACK_F32X2(lo, hi, acc2[i][1]);
        o[2] = __uint_as_float(lo) * inv; o[3] = __uint_as_float(hi) * inv;
        *(float4*)&Og[(size_t)(q0 + ty * 4 + i) * DM_ + tx * 4] =
            make_float4(o[0], o[1], o[2], o[3]);
    }
}

// ---------------------------------------------------------------------------
extern "C" void kernel_launch(void* const* d_in, const int* in_sizes, int n_in,
                              void* d_out, int out_size)
{
    const float* X   = (const float*)d_in[0];  // queries [2,2048,1024]
    const float* Wq  = (const float*)d_in[1];  // [1024,1024]
    const float* Wkv = (const float*)d_in[2];  // [1024,2048]
    const float* Wo  = (const float*)d_in[3];  // [1024,1024]
    const float* bo  = (const float*)d_in[4];  // [1024]
    float* out = (float*)d_out;
    (void)in_sizes; (void)n_in; (void)out_size;

    float* o;
    cudaGetSymbolAddress((void**)&o, g_O);

    cudaFuncSetAttribute(attn_kernel,
                         cudaFuncAttributeMaxDynamicSharedMemorySize, ASMEM);

    qkv_kernel<<<dim3(24, 32), 256>>>(X, Wq, Wkv);          // Q + K + V proj
    attn_kernel<<<dim3(32, 16, 2), 256, ASMEM>>>();
    gemm_kernel<<<dim3(8, 32), 256>>>(o, Wo, 1024, bo, out); // out proj
}